// round 10
// baseline (speedup 1.0000x reference)
#include <cuda_runtime.h>
#include <cstdint>

typedef unsigned long long ull;

// Packed fp32x2 FMA (sm_100+/sm_103a; ptxas never auto-generates this)
#define FMA2(d, a, b, c) \
    asm("fma.rn.f32x2 %0, %1, %2, %3;" : "=l"(d) : "l"(a), "l"(b), "l"(c))
#define ADD2(d, a, b) \
    asm("add.rn.f32x2 %0, %1, %2;" : "=l"(d) : "l"(a), "l"(b))

__device__ __forceinline__ ull pack2(float lo, float hi) {
    ull r; asm("mov.b64 %0, {%1, %2};" : "=l"(r) : "f"(lo), "f"(hi)); return r;
}
__device__ __forceinline__ void unpack2(ull v, float& lo, float& hi) {
    asm("mov.b64 {%0, %1}, %2;" : "=f"(lo), "=f"(hi) : "l"(v));
}

__device__ __forceinline__ void cp_async16cg(void* smem_dst, const void* gsrc) {
    unsigned s = (unsigned)__cvta_generic_to_shared(smem_dst);
    asm volatile("cp.async.cg.shared.global [%0], [%1], 16;" :: "r"(s), "l"(gsrc));
}
#define CP_COMMIT()  asm volatile("cp.async.commit_group;")
#define CP_WAIT(n)   asm volatile("cp.async.wait_group %0;" :: "n"(n))

// Problem constants
constexpr int B  = 8;
constexpr int C  = 256;
constexpr int M  = 64;
constexpr int H  = 128, W = 128, HW = H * W;       // input spatial
constexpr int KK = 25;                              // 5x5 window
constexpr int nH = 64, nW = 64, nHW = nH * nW;      // output spatial

// Scratch (device globals — no allocation allowed)
__device__ float g_mid[(size_t)B * M * HW];    // conv1x1 output (33.5 MB)
__device__ float g_ker[(size_t)B * KK * nHW];  // softmax kernel (3.3 MB)

// ---------------------------------------------------------------------------
// Kernel 1: 1x1 conv (R5-proven version — 98.5us)
// ---------------------------------------------------------------------------
constexpr int PT1 = 256;    // pixels per block
constexpr int KC1 = 16;     // channels per chunk
constexpr int SM1_W = 0;                    // w_s[c][m]: 256*64*4   = 65536
constexpr int SM1_X = 65536;                // x_s[2][16][256 floats] = 32768
constexpr int SM1_TOTAL = 65536 + 32768;    // 98304

__device__ __forceinline__ uint32_t sw128(uint32_t o) {
    return o ^ ((o >> 3) & 0x70u);
}

__global__ void __launch_bounds__(256, 2) k1_conv1x1(
    const float* __restrict__ x, const float* __restrict__ w1,
    const float* __restrict__ b1)
{
    extern __shared__ char smem[];
    float* w_s = (float*)(smem + SM1_W);
    char*  x_s = smem + SM1_X;

    const int t    = threadIdx.x;
    const int bx   = blockIdx.x;          // 512 blocks
    const int b    = bx >> 6;
    const int p0   = (bx & 63) * PT1;
    const int warp = t >> 5, lane = t & 31;
    const int m0   = warp * 8;
    const int px0  = lane * 8;

    const float* xb = x + (size_t)(b * C) * HW + p0;

    const int xcc = t >> 4;
    const int xc4 = t & 15;
    uint32_t dsw[4];
#pragma unroll
    for (int j = 0; j < 4; j++) dsw[j] = sw128((uint32_t)((xc4 + j * 16) * 16));

    const uint32_t s1 = sw128((uint32_t)(lane * 32));
    const uint32_t s2 = sw128((uint32_t)(lane * 32 + 16));

#pragma unroll
    for (int j = 0; j < 4; j++)
        cp_async16cg(x_s + xcc * 1024 + dsw[j],
                     xb + (size_t)xcc * HW + xc4 * 4 + j * 64);
    CP_COMMIT();
#pragma unroll
    for (int j = 0; j < 4; j++)
        cp_async16cg(x_s + 16384 + xcc * 1024 + dsw[j],
                     xb + (size_t)(KC1 + xcc) * HW + xc4 * 4 + j * 64);
    CP_COMMIT();

#pragma unroll
    for (int it = 0; it < 16; it++) {
        int gid = it * 256 + t;
        int m  = gid & 63;
        int c4 = (gid >> 6) * 4;
        float4 wq = *(const float4*)&w1[m * C + c4];
        w_s[(c4 + 0) * 64 + m] = wq.x;
        w_s[(c4 + 1) * 64 + m] = wq.y;
        w_s[(c4 + 2) * 64 + m] = wq.z;
        w_s[(c4 + 3) * 64 + m] = wq.w;
    }

    ull acc[4][8];
#pragma unroll
    for (int i = 0; i < 4; i++)
#pragma unroll
        for (int p = 0; p < 8; p++) acc[i][p] = 0ULL;

    CP_WAIT(1);
    __syncthreads();

    int cur = 0;
#pragma unroll 1
    for (int ch = 0; ch < 16; ch++) {
        const char* xrow = x_s + cur * 16384;
        const float* wc  = w_s + (ch * KC1) * 64 + m0;
#pragma unroll
        for (int cc = 0; cc < KC1; cc++) {
            ulonglong2 wv0 = *(const ulonglong2*)(wc + cc * 64);
            ulonglong2 wv1 = *(const ulonglong2*)(wc + cc * 64 + 4);
            float4 xa = *(const float4*)(xrow + cc * 1024 + s1);
            float4 xc = *(const float4*)(xrow + cc * 1024 + s2);
            ull xs[8];
            xs[0] = pack2(xa.x, xa.x); xs[1] = pack2(xa.y, xa.y);
            xs[2] = pack2(xa.z, xa.z); xs[3] = pack2(xa.w, xa.w);
            xs[4] = pack2(xc.x, xc.x); xs[5] = pack2(xc.y, xc.y);
            xs[6] = pack2(xc.z, xc.z); xs[7] = pack2(xc.w, xc.w);
#pragma unroll
            for (int p = 0; p < 8; p++) {
                FMA2(acc[0][p], wv0.x, xs[p], acc[0][p]);
                FMA2(acc[1][p], wv0.y, xs[p], acc[1][p]);
                FMA2(acc[2][p], wv1.x, xs[p], acc[2][p]);
                FMA2(acc[3][p], wv1.y, xs[p], acc[3][p]);
            }
        }
        __syncthreads();
        if (ch < 14) {
            const int cnext = (ch + 2) * KC1;
#pragma unroll
            for (int j = 0; j < 4; j++)
                cp_async16cg(x_s + cur * 16384 + xcc * 1024 + dsw[j],
                             xb + (size_t)(cnext + xcc) * HW + xc4 * 4 + j * 64);
            CP_COMMIT();
            CP_WAIT(1);
        } else {
            CP_WAIT(0);
        }
        __syncthreads();
        cur ^= 1;
    }

#pragma unroll
    for (int i = 0; i < 4; i++) {
        ull bp = pack2(b1[m0 + 2 * i], b1[m0 + 2 * i + 1]);
        float lo[8], hi[8];
#pragma unroll
        for (int p = 0; p < 8; p++) {
            ull v; ADD2(v, acc[i][p], bp);
            unpack2(v, lo[p], hi[p]);
        }
        size_t base = ((size_t)(b * M + m0 + 2 * i)) * HW + p0 + px0;
        *(float4*)&g_mid[base]          = make_float4(lo[0], lo[1], lo[2], lo[3]);
        *(float4*)&g_mid[base + 4]      = make_float4(lo[4], lo[5], lo[6], lo[7]);
        *(float4*)&g_mid[base + HW]     = make_float4(hi[0], hi[1], hi[2], hi[3]);
        *(float4*)&g_mid[base + HW + 4] = make_float4(hi[4], hi[5], hi[6], hi[7]);
    }
}

// ---------------------------------------------------------------------------
// Kernel 2: 3x3 conv s2 p1, 64->25, + bias + softmax (R7-proven version).
// ---------------------------------------------------------------------------
__global__ void __launch_bounds__(128) k2_encoder(
    const float* __restrict__ w2, const float* __restrict__ b2)
{
    __shared__ float2 ms[2][2][17][37];   // [buf][cpair][row][col]
    __shared__ float2 ws[2][2][9][26];    // [buf][cpair][j][k]

    const int t  = threadIdx.x;
    const int b  = blockIdx.z;
    const int h0 = blockIdx.y * 8;
    const int w0 = blockIdx.x * 16;
    const int ty = t >> 4;
    const int tx = t & 15;

    constexpr int MS_BUF = 2 * 17 * 37;
    constexpr int WS_BUF = 2 * 9 * 26;
    float2* msb = &ms[0][0][0][0];
    float2* wsb = &ws[0][0][0][0];

    int ms_off[9], ms_di[9];
#pragma unroll
    for (int s = 0; s < 9; s++) {
        int idx = t + s * 128;
        ms_off[s] = -1; ms_di[s] = -1;
        if (idx < 1122) {
            int cp = idx / 561, r = idx % 561;
            int i = r / 33, jj = r % 33;
            int ih = 2 * h0 - 1 + i, iw = 2 * w0 - 1 + jj;
            ms_di[s] = (cp * 17 + i) * 37 + jj;
            if ((unsigned)ih < 128u && (unsigned)iw < 128u)
                ms_off[s] = (b * M + 2 * cp) * HW + ih * W + iw;
        }
    }
    int ws_src[4], ws_di[4];
#pragma unroll
    for (int s = 0; s < 4; s++) {
        int idx = t + s * 128;
        ws_src[s] = -1; ws_di[s] = -1;
        if (idx < 450) {
            int cp = idx / 225, r = idx % 225;
            int j = r / 25, k = r % 25;
            ws_src[s] = (k * M + 2 * cp) * 9 + j;
            ws_di[s] = (cp * 9 + j) * 26 + k;
        }
    }

    float2 mv[9], wvv[4];
#pragma unroll
    for (int s = 0; s < 9; s++) {
        mv[s] = make_float2(0.f, 0.f);
        if (ms_off[s] >= 0) {
            mv[s].x = g_mid[ms_off[s]];
            mv[s].y = g_mid[ms_off[s] + HW];
        }
    }
#pragma unroll
    for (int s = 0; s < 4; s++)
        if (ws_src[s] >= 0)
            wvv[s] = make_float2(w2[ws_src[s]], w2[ws_src[s] + 9]);
#pragma unroll
    for (int s = 0; s < 9; s++) if (ms_di[s] >= 0) msb[ms_di[s]] = mv[s];
#pragma unroll
    for (int s = 0; s < 4; s++) if (ws_di[s] >= 0) wsb[ws_di[s]] = wvv[s];
    __syncthreads();

    ull acc[25];
#pragma unroll
    for (int k = 0; k < 25; k++) acc[k] = 0ULL;

    int cur = 0;
#pragma unroll 1
    for (int chk = 0; chk < 16; chk++) {
        if (chk < 15) {
            const int moff = (chk + 1) * 4 * HW;
#pragma unroll
            for (int s = 0; s < 9; s++) {
                mv[s] = make_float2(0.f, 0.f);
                if (ms_off[s] >= 0) {
                    mv[s].x = g_mid[ms_off[s] + moff];
                    mv[s].y = g_mid[ms_off[s] + moff + HW];
                }
            }
            const int woff = (chk + 1) * 36;
#pragma unroll
            for (int s = 0; s < 4; s++)
                if (ws_src[s] >= 0)
                    wvv[s] = make_float2(w2[ws_src[s] + woff],
                                         w2[ws_src[s] + woff + 9]);
        }

#pragma unroll
        for (int cp = 0; cp < 2; cp++) {
            ull xp[9];
#pragma unroll
            for (int i = 0; i < 3; i++)
#pragma unroll
                for (int j = 0; j < 3; j++)
                    xp[i * 3 + j] = *(const ull*)&ms[cur][cp][2 * ty + i][2 * tx + j];
#pragma unroll
            for (int j9 = 0; j9 < 9; j9++) {
#pragma unroll
                for (int k2 = 0; k2 < 12; k2++) {
                    ulonglong2 wq = *(const ulonglong2*)&ws[cur][cp][j9][2 * k2];
                    FMA2(acc[2*k2  ], wq.x, xp[j9], acc[2*k2  ]);
                    FMA2(acc[2*k2+1], wq.y, xp[j9], acc[2*k2+1]);
                }
                ull wl = *(const ull*)&ws[cur][cp][j9][24];
                FMA2(acc[24], wl, xp[j9], acc[24]);
            }
        }

        if (chk < 15) {
            const int nb = cur ^ 1;
#pragma unroll
            for (int s = 0; s < 9; s++)
                if (ms_di[s] >= 0) msb[nb * MS_BUF + ms_di[s]] = mv[s];
#pragma unroll
            for (int s = 0; s < 4; s++)
                if (ws_di[s] >= 0) wsb[nb * WS_BUF + ws_di[s]] = wvv[s];
            __syncthreads();
        }
        cur ^= 1;
    }

    float lg[25];
#pragma unroll
    for (int k = 0; k < 25; k++) {
        float a, bq; unpack2(acc[k], a, bq);
        lg[k] = a + bq + b2[k];
    }
    float mx = lg[0];
#pragma unroll
    for (int k = 1; k < 25; k++) mx = fmaxf(mx, lg[k]);
    float e[25], sum = 0.f;
#pragma unroll
    for (int k = 0; k < 25; k++) { e[k] = __expf(lg[k] - mx); sum += e[k]; }
    const float inv = 1.f / sum;
    const int h = h0 + ty, w = w0 + tx;
    const size_t base = ((size_t)b * KK) * nHW + h * nW + w;
#pragma unroll
    for (int k = 0; k < 25; k++)
        g_ker[base + (size_t)k * nHW] = e[k] * inv;
}

// ---------------------------------------------------------------------------
// Kernel 3: softmax-weighted 5x5 window sum.  New: kp weights in smem
// (frees 50 regs), packed slot tables, 32 channels/block (z=64), target
// 3 blocks/SM for latency coverage.
// ---------------------------------------------------------------------------
constexpr int SM3_XI = 0;                       // 2 bufs x 2660 float2 = 42560
constexpr int SM3_KP = 42560;                   // 256*25*4 = 25600
constexpr int SM3_TOTAL = 42560 + 25600;        // 68160
constexpr int XI_BUF = 2 * 35 * 38;             // float2 per buffer

__global__ void __launch_bounds__(256, 3) k3_apply(
    const float* __restrict__ x, float* __restrict__ out)
{
    extern __shared__ char smem3[];
    float2* xib  = (float2*)(smem3 + SM3_XI);
    float*  kp_s = (float*)(smem3 + SM3_KP);

    const int t  = threadIdx.x;
    const int bz = blockIdx.z;            // 64 = b*8 + cg
    const int b  = bz >> 3;
    const int cbase = (bz & 7) * 32;
    const int h0 = blockIdx.y * 16, w0 = blockIdx.x * 16;
    const int py = t >> 4, px = t & 15;
    const int h = h0 + py, w = w0 + px;

    // kp -> smem (per-thread 25, stride-25 conflict-free on read)
    {
        const size_t kb = ((size_t)b * KK) * nHW + h * nW + w;
#pragma unroll
        for (int k = 0; k < 25; k++)
            kp_s[t * 25 + k] = g_ker[kb + (size_t)k * nHW];
    }

    const int ir0 = 2 * h0 - 2, ic0 = 2 * w0 - 2;
    const float* xb = x + ((size_t)(b * C + cbase)) * HW;

    // packed slot tables: bits[27:12]=xoff (0xFFFF=invalid), bits[11:0]=xdi
    int slot[10];
#pragma unroll
    for (int s = 0; s < 10; s++) {
        int idx = t + s * 256;
        slot[s] = -1;
        if (idx < 2450) {
            int cp = (idx >= 1225) ? 1 : 0;
            int rr = idx - cp * 1225;
            int r = rr / 35, cc = rr - r * 35;
            int ir = ir0 + r, ic = ic0 + cc;
            int xdi = (cp * 35 + r) * 38 + cc;
            int xo = 0xFFFF;
            if ((unsigned)ir < 128u && (unsigned)ic < 128u)
                xo = cp * 2 * HW + ir * W + ic;
            slot[s] = (xo << 12) | xdi;
        }
    }

    float2 xv[10];
    // prologue: stage 0
#pragma unroll
    for (int s = 0; s < 10; s++) {
        xv[s] = make_float2(0.f, 0.f);
        if (slot[s] >= 0) {
            int xo = (unsigned)slot[s] >> 12;
            if (xo != 0xFFFF) {
                xv[s].x = xb[xo];
                xv[s].y = xb[xo + HW];
            }
        }
    }
#pragma unroll
    for (int s = 0; s < 10; s++)
        if (slot[s] >= 0) xib[slot[s] & 0xFFF] = xv[s];
    __syncthreads();

    int cur = 0;
#pragma unroll 1
    for (int it = 0; it < 8; it++) {              // 8 stages x 4 channels
        if (it < 7) {
            const int coff = (it + 1) * 4 * HW;
#pragma unroll
            for (int s = 0; s < 10; s++) {
                xv[s] = make_float2(0.f, 0.f);
                if (slot[s] >= 0) {
                    int xo = (unsigned)slot[s] >> 12;
                    if (xo != 0xFFFF) {
                        xv[s].x = xb[xo + coff];
                        xv[s].y = xb[xo + coff + HW];
                    }
                }
            }
        }

        // compute 2 cpairs from buffer cur; kp re-read from smem per k
        ull a[2][5];
#pragma unroll
        for (int cp = 0; cp < 2; cp++)
#pragma unroll
            for (int i = 0; i < 5; i++) a[cp][i] = 0ULL;

        const float2* xr = xib + cur * XI_BUF;
#pragma unroll
        for (int k = 0; k < 25; k++) {
            const int i = k / 5, j = k % 5;
            float kv = kp_s[t * 25 + k];
            ull kvp = pack2(kv, kv);
            ull x0 = *(const ull*)&xr[(0 * 35 + 2 * py + i) * 38 + 2 * px + j];
            ull x1 = *(const ull*)&xr[(1 * 35 + 2 * py + i) * 38 + 2 * px + j];
            FMA2(a[0][k % 5], kvp, x0, a[0][k % 5]);
            FMA2(a[1][k % 5], kvp, x1, a[1][k % 5]);
        }

        const int c = cbase + it * 4;
#pragma unroll
        for (int cp = 0; cp < 2; cp++) {
            ull s01, s23, ssum;
            ADD2(s01, a[cp][0], a[cp][1]);
            ADD2(s23, a[cp][2], a[cp][3]);
            ADD2(s01, s01, s23);
            ADD2(ssum, s01, a[cp][4]);
            float o0, o1; unpack2(ssum, o0, o1);
            const size_t obase = ((size_t)(b * C + c + 2 * cp)) * nHW + h * nW + w;
            out[obase]       = o0;
            out[obase + nHW] = o1;
        }

        if (it < 7) {
            const int nb = cur ^ 1;
#pragma unroll
            for (int s = 0; s < 10; s++)
                if (slot[s] >= 0) xib[nb * XI_BUF + (slot[s] & 0xFFF)] = xv[s];
            __syncthreads();
        }
        cur ^= 1;
    }
}

// ---------------------------------------------------------------------------
extern "C" void kernel_launch(void* const* d_in, const int* in_sizes, int n_in,
                              void* d_out, int out_size)
{
    (void)in_sizes; (void)n_in; (void)out_size;
    const float* x  = (const float*)d_in[0];
    const float* w1 = (const float*)d_in[1];
    const float* b1 = (const float*)d_in[2];
    const float* w2 = (const float*)d_in[3];
    const float* b2 = (const float*)d_in[4];
    float* out = (float*)d_out;

    cudaFuncSetAttribute(k1_conv1x1,
                         cudaFuncAttributeMaxDynamicSharedMemorySize, SM1_TOTAL);
    cudaFuncSetAttribute(k3_apply,
                         cudaFuncAttributeMaxDynamicSharedMemorySize, SM3_TOTAL);
    k1_conv1x1<<<512, 256, SM1_TOTAL>>>(x, w1, b1);
    k2_encoder<<<dim3(4, 8, 8), 128>>>(w2, b2);
    k3_apply<<<dim3(4, 4, 64), 256, SM3_TOTAL>>>(x, out);
}

// round 11
// speedup vs baseline: 1.1203x; 1.1203x over previous
#include <cuda_runtime.h>
#include <cstdint>

typedef unsigned long long ull;

// Packed fp32x2 FMA (sm_100+/sm_103a; ptxas never auto-generates this)
#define FMA2(d, a, b, c) \
    asm("fma.rn.f32x2 %0, %1, %2, %3;" : "=l"(d) : "l"(a), "l"(b), "l"(c))
#define ADD2(d, a, b) \
    asm("add.rn.f32x2 %0, %1, %2;" : "=l"(d) : "l"(a), "l"(b))

__device__ __forceinline__ ull pack2(float lo, float hi) {
    ull r; asm("mov.b64 %0, {%1, %2};" : "=l"(r) : "f"(lo), "f"(hi)); return r;
}
__device__ __forceinline__ void unpack2(ull v, float& lo, float& hi) {
    asm("mov.b64 {%0, %1}, %2;" : "=f"(lo), "=f"(hi) : "l"(v));
}

__device__ __forceinline__ void cp_async16cg(void* smem_dst, const void* gsrc) {
    unsigned s = (unsigned)__cvta_generic_to_shared(smem_dst);
    asm volatile("cp.async.cg.shared.global [%0], [%1], 16;" :: "r"(s), "l"(gsrc));
}
#define CP_COMMIT()  asm volatile("cp.async.commit_group;")
#define CP_WAIT(n)   asm volatile("cp.async.wait_group %0;" :: "n"(n))

// Problem constants
constexpr int B  = 8;
constexpr int C  = 256;
constexpr int M  = 64;
constexpr int H  = 128, W = 128, HW = H * W;       // input spatial
constexpr int KK = 25;                              // 5x5 window
constexpr int nH = 64, nW = 64, nHW = nH * nW;      // output spatial

// Scratch (device globals — no allocation allowed)
__device__ float g_mid[(size_t)B * M * HW];    // conv1x1 output (33.5 MB)
__device__ float g_ker[(size_t)B * KK * nHW];  // softmax kernel (3.3 MB)
__device__ float g_wT[C * M];                  // transposed w1 [c][m] (64 KB)

__device__ __forceinline__ uint32_t sw128(uint32_t o) {
    return o ^ ((o >> 3) & 0x70u);
}

// ---------------------------------------------------------------------------
// Kernel 0: transpose w1 [m][c] -> g_wT [c][m]  (one-time, 64 KB)
// ---------------------------------------------------------------------------
__global__ void __launch_bounds__(256) k0_transpose(const float* __restrict__ w1)
{
    int idx = blockIdx.x * 256 + threadIdx.x;   // 16384
    int m = idx >> 8, c = idx & 255;
    g_wT[c * 64 + m] = w1[idx];
}

// ---------------------------------------------------------------------------
// Kernel 1: 1x1 conv  C=256 -> M=64 + bias.  GEMM [64,256] x [256, B*HW].
// Thread tile 8m x 8px (m-pairs in f32x2 lanes).  Weights via warp-uniform
// LDG.128 from g_wT (L1-resident; x streams bypass L1 via cp.async.cg).
// x: 4-buffer cp.async pipeline, issue 2 ahead, ONE sync per chunk.
// ---------------------------------------------------------------------------
constexpr int PT1 = 256;    // pixels per block
constexpr int KC1 = 16;     // channels per chunk
constexpr int SM1_TOTAL = 4 * 16384;   // 64 KB: x_s[4][16][256 floats]

__global__ void __launch_bounds__(256, 2) k1_conv1x1(
    const float* __restrict__ x, const float* __restrict__ b1)
{
    extern __shared__ char smem[];
    char* x_s = smem;

    const int t    = threadIdx.x;
    const int bx   = blockIdx.x;          // 512 blocks
    const int b    = bx >> 6;
    const int p0   = (bx & 63) * PT1;
    const int warp = t >> 5, lane = t & 31;
    const int m0   = warp * 8;
    const int px0  = lane * 8;

    const float* xb = x + (size_t)(b * C) * HW + p0;

    // x-fill roles: cc = t>>4 (16 channels), 4 float4s per thread per chunk
    const int xcc = t >> 4;
    const int xc4 = t & 15;
    uint32_t dsw[4];
#pragma unroll
    for (int j = 0; j < 4; j++) dsw[j] = sw128((uint32_t)((xc4 + j * 16) * 16));

    const uint32_t s1 = sw128((uint32_t)(lane * 32));
    const uint32_t s2 = sw128((uint32_t)(lane * 32 + 16));

    // ---- prologue: chunks 0,1 ----
#pragma unroll
    for (int j = 0; j < 4; j++)
        cp_async16cg(x_s + xcc * 1024 + dsw[j],
                     xb + (size_t)xcc * HW + xc4 * 4 + j * 64);
    CP_COMMIT();
#pragma unroll
    for (int j = 0; j < 4; j++)
        cp_async16cg(x_s + 16384 + xcc * 1024 + dsw[j],
                     xb + (size_t)(KC1 + xcc) * HW + xc4 * 4 + j * 64);
    CP_COMMIT();

    ull acc[4][8];
#pragma unroll
    for (int i = 0; i < 4; i++)
#pragma unroll
        for (int p = 0; p < 8; p++) acc[i][p] = 0ULL;

    int cur = 0;
#pragma unroll 1
    for (int ch = 0; ch < 16; ch++) {
        // issue chunk ch+2 into buf[(ch+2)&3] (last read at iter ch-2; sealed
        // by iter ch-1's barrier), then wait for chunk ch, then ONE barrier.
        if (ch < 14) {
            const int cnx = (ch + 2) * KC1;
            char* dst = x_s + ((ch + 2) & 3) * 16384;
#pragma unroll
            for (int j = 0; j < 4; j++)
                cp_async16cg(dst + xcc * 1024 + dsw[j],
                             xb + (size_t)(cnx + xcc) * HW + xc4 * 4 + j * 64);
            CP_COMMIT();
            CP_WAIT(2);
        } else if (ch == 14) {
            CP_WAIT(1);
        } else {
            CP_WAIT(0);
        }
        __syncthreads();

        const char* xrow = x_s + cur * 16384;
        const float* wc  = g_wT + (ch * KC1) * 64 + m0;
#pragma unroll
        for (int cc = 0; cc < KC1; cc++) {
            ulonglong2 wv0 = *(const ulonglong2*)(wc + cc * 64);      // m-pairs 0,1
            ulonglong2 wv1 = *(const ulonglong2*)(wc + cc * 64 + 4);  // m-pairs 2,3
            float4 xa = *(const float4*)(xrow + cc * 1024 + s1);
            float4 xc = *(const float4*)(xrow + cc * 1024 + s2);
            ull xs[8];
            xs[0] = pack2(xa.x, xa.x); xs[1] = pack2(xa.y, xa.y);
            xs[2] = pack2(xa.z, xa.z); xs[3] = pack2(xa.w, xa.w);
            xs[4] = pack2(xc.x, xc.x); xs[5] = pack2(xc.y, xc.y);
            xs[6] = pack2(xc.z, xc.z); xs[7] = pack2(xc.w, xc.w);
#pragma unroll
            for (int p = 0; p < 8; p++) {
                FMA2(acc[0][p], wv0.x, xs[p], acc[0][p]);
                FMA2(acc[1][p], wv0.y, xs[p], acc[1][p]);
                FMA2(acc[2][p], wv1.x, xs[p], acc[2][p]);
                FMA2(acc[3][p], wv1.y, xs[p], acc[3][p]);
            }
        }
        cur = (cur + 1) & 3;
    }

    // ---- epilogue: bias + store ----
#pragma unroll
    for (int i = 0; i < 4; i++) {
        ull bp = pack2(b1[m0 + 2 * i], b1[m0 + 2 * i + 1]);
        float lo[8], hi[8];
#pragma unroll
        for (int p = 0; p < 8; p++) {
            ull v; ADD2(v, acc[i][p], bp);
            unpack2(v, lo[p], hi[p]);
        }
        size_t base = ((size_t)(b * M + m0 + 2 * i)) * HW + p0 + px0;
        *(float4*)&g_mid[base]          = make_float4(lo[0], lo[1], lo[2], lo[3]);
        *(float4*)&g_mid[base + 4]      = make_float4(lo[4], lo[5], lo[6], lo[7]);
        *(float4*)&g_mid[base + HW]     = make_float4(hi[0], hi[1], hi[2], hi[3]);
        *(float4*)&g_mid[base + HW + 4] = make_float4(hi[4], hi[5], hi[6], hi[7]);
    }
}

// ---------------------------------------------------------------------------
// Kernel 2: 3x3 conv s2 p1, 64->25, + bias + softmax (R7-proven, verbatim).
// ---------------------------------------------------------------------------
__global__ void __launch_bounds__(128) k2_encoder(
    const float* __restrict__ w2, const float* __restrict__ b2)
{
    __shared__ float2 ms[2][2][17][37];   // [buf][cpair][row][col]
    __shared__ float2 ws[2][2][9][26];    // [buf][cpair][j][k]

    const int t  = threadIdx.x;
    const int b  = blockIdx.z;
    const int h0 = blockIdx.y * 8;
    const int w0 = blockIdx.x * 16;
    const int ty = t >> 4;
    const int tx = t & 15;

    constexpr int MS_BUF = 2 * 17 * 37;
    constexpr int WS_BUF = 2 * 9 * 26;
    float2* msb = &ms[0][0][0][0];
    float2* wsb = &ws[0][0][0][0];

    int ms_off[9], ms_di[9];
#pragma unroll
    for (int s = 0; s < 9; s++) {
        int idx = t + s * 128;
        ms_off[s] = -1; ms_di[s] = -1;
        if (idx < 1122) {
            int cp = idx / 561, r = idx % 561;
            int i = r / 33, jj = r % 33;
            int ih = 2 * h0 - 1 + i, iw = 2 * w0 - 1 + jj;
            ms_di[s] = (cp * 17 + i) * 37 + jj;
            if ((unsigned)ih < 128u && (unsigned)iw < 128u)
                ms_off[s] = (b * M + 2 * cp) * HW + ih * W + iw;
        }
    }
    int ws_src[4], ws_di[4];
#pragma unroll
    for (int s = 0; s < 4; s++) {
        int idx = t + s * 128;
        ws_src[s] = -1; ws_di[s] = -1;
        if (idx < 450) {
            int cp = idx / 225, r = idx % 225;
            int j = r / 25, k = r % 25;
            ws_src[s] = (k * M + 2 * cp) * 9 + j;
            ws_di[s] = (cp * 9 + j) * 26 + k;
        }
    }

    float2 mv[9], wvv[4];
#pragma unroll
    for (int s = 0; s < 9; s++) {
        mv[s] = make_float2(0.f, 0.f);
        if (ms_off[s] >= 0) {
            mv[s].x = g_mid[ms_off[s]];
            mv[s].y = g_mid[ms_off[s] + HW];
        }
    }
#pragma unroll
    for (int s = 0; s < 4; s++)
        if (ws_src[s] >= 0)
            wvv[s] = make_float2(w2[ws_src[s]], w2[ws_src[s] + 9]);
#pragma unroll
    for (int s = 0; s < 9; s++) if (ms_di[s] >= 0) msb[ms_di[s]] = mv[s];
#pragma unroll
    for (int s = 0; s < 4; s++) if (ws_di[s] >= 0) wsb[ws_di[s]] = wvv[s];
    __syncthreads();

    ull acc[25];
#pragma unroll
    for (int k = 0; k < 25; k++) acc[k] = 0ULL;

    int cur = 0;
#pragma unroll 1
    for (int chk = 0; chk < 16; chk++) {
        if (chk < 15) {
            const int moff = (chk + 1) * 4 * HW;
#pragma unroll
            for (int s = 0; s < 9; s++) {
                mv[s] = make_float2(0.f, 0.f);
                if (ms_off[s] >= 0) {
                    mv[s].x = g_mid[ms_off[s] + moff];
                    mv[s].y = g_mid[ms_off[s] + moff + HW];
                }
            }
            const int woff = (chk + 1) * 36;
#pragma unroll
            for (int s = 0; s < 4; s++)
                if (ws_src[s] >= 0)
                    wvv[s] = make_float2(w2[ws_src[s] + woff],
                                         w2[ws_src[s] + woff + 9]);
        }

#pragma unroll
        for (int cp = 0; cp < 2; cp++) {
            ull xp[9];
#pragma unroll
            for (int i = 0; i < 3; i++)
#pragma unroll
                for (int j = 0; j < 3; j++)
                    xp[i * 3 + j] = *(const ull*)&ms[cur][cp][2 * ty + i][2 * tx + j];
#pragma unroll
            for (int j9 = 0; j9 < 9; j9++) {
#pragma unroll
                for (int k2 = 0; k2 < 12; k2++) {
                    ulonglong2 wq = *(const ulonglong2*)&ws[cur][cp][j9][2 * k2];
                    FMA2(acc[2*k2  ], wq.x, xp[j9], acc[2*k2  ]);
                    FMA2(acc[2*k2+1], wq.y, xp[j9], acc[2*k2+1]);
                }
                ull wl = *(const ull*)&ws[cur][cp][j9][24];
                FMA2(acc[24], wl, xp[j9], acc[24]);
            }
        }

        if (chk < 15) {
            const int nb = cur ^ 1;
#pragma unroll
            for (int s = 0; s < 9; s++)
                if (ms_di[s] >= 0) msb[nb * MS_BUF + ms_di[s]] = mv[s];
#pragma unroll
            for (int s = 0; s < 4; s++)
                if (ws_di[s] >= 0) wsb[nb * WS_BUF + ws_di[s]] = wvv[s];
            __syncthreads();
        }
        cur ^= 1;
    }

    float lg[25];
#pragma unroll
    for (int k = 0; k < 25; k++) {
        float a, bq; unpack2(acc[k], a, bq);
        lg[k] = a + bq + b2[k];
    }
    float mx = lg[0];
#pragma unroll
    for (int k = 1; k < 25; k++) mx = fmaxf(mx, lg[k]);
    float e[25], sum = 0.f;
#pragma unroll
    for (int k = 0; k < 25; k++) { e[k] = __expf(lg[k] - mx); sum += e[k]; }
    const float inv = 1.f / sum;
    const int h = h0 + ty, w = w0 + tx;
    const size_t base = ((size_t)b * KK) * nHW + h * nW + w;
#pragma unroll
    for (int k = 0; k < 25; k++)
        g_ker[base + (size_t)k * nHW] = e[k] * inv;
}

// ---------------------------------------------------------------------------
// Kernel 3: softmax-weighted 5x5 window sum (R7-proven, verbatim).
// ---------------------------------------------------------------------------
__global__ void __launch_bounds__(256) k3_apply(
    const float* __restrict__ x, float* __restrict__ out)
{
    __shared__ float2 xi[2][2][35][38];   // [buf][cpair][row][col]

    const int t  = threadIdx.x;
    const int bz = blockIdx.z;
    const int b  = bz >> 2;
    const int cbase = (bz & 3) * 64;
    const int h0 = blockIdx.y * 16, w0 = blockIdx.x * 16;
    const int py = t >> 4, px = t & 15;
    const int h = h0 + py, w = w0 + px;

    constexpr int XI_BUF = 2 * 35 * 38;
    float2* xib = &xi[0][0][0][0];

    ull kp[25];
#pragma unroll
    for (int k = 0; k < 25; k++) {
        float kv = g_ker[((size_t)(b * KK + k)) * nHW + h * nW + w];
        kp[k] = pack2(kv, kv);
    }

    const int ir0 = 2 * h0 - 2, ic0 = 2 * w0 - 2;
    const float* xb = x + ((size_t)(b * C + cbase)) * HW;

    int xoff[10], xdi[10];
#pragma unroll
    for (int s = 0; s < 10; s++) {
        int idx = t + s * 256;
        xoff[s] = -1; xdi[s] = -1;
        if (idx < 2450) {
            int cp = (idx >= 1225) ? 1 : 0;
            int rr = idx - cp * 1225;
            int r = rr / 35, cc = rr - r * 35;
            int ir = ir0 + r, ic = ic0 + cc;
            xdi[s] = (cp * 35 + r) * 38 + cc;
            if ((unsigned)ir < 128u && (unsigned)ic < 128u)
                xoff[s] = cp * 2 * HW + ir * W + ic;
        }
    }

    float2 xv[10];
#pragma unroll
    for (int s = 0; s < 10; s++) {
        xv[s] = make_float2(0.f, 0.f);
        if (xoff[s] >= 0) {
            xv[s].x = xb[xoff[s]];
            xv[s].y = xb[xoff[s] + HW];
        }
    }
#pragma unroll
    for (int s = 0; s < 10; s++) if (xdi[s] >= 0) xib[xdi[s]] = xv[s];
    __syncthreads();

    int cur = 0;
#pragma unroll 1
    for (int it = 0; it < 16; it++) {
        if (it < 15) {
            const int coff = (it + 1) * 4 * HW;
#pragma unroll
            for (int s = 0; s < 10; s++) {
                xv[s] = make_float2(0.f, 0.f);
                if (xoff[s] >= 0) {
                    xv[s].x = xb[xoff[s] + coff];
                    xv[s].y = xb[xoff[s] + coff + HW];
                }
            }
        }

        const int c = cbase + it * 4;
#pragma unroll
        for (int cp = 0; cp < 2; cp++) {
            ull a[5];
#pragma unroll
            for (int i = 0; i < 5; i++) a[i] = 0ULL;
#pragma unroll
            for (int i = 0; i < 5; i++)
#pragma unroll
                for (int j = 0; j < 5; j++) {
                    ull xvv = *(const ull*)&xi[cur][cp][2 * py + i][2 * px + j];
                    const int k = i * 5 + j;
                    FMA2(a[k % 5], kp[k], xvv, a[k % 5]);
                }
            ull s01, s23, ssum;
            ADD2(s01, a[0], a[1]);
            ADD2(s23, a[2], a[3]);
            ADD2(s01, s01, s23);
            ADD2(ssum, s01, a[4]);
            float o0, o1; unpack2(ssum, o0, o1);
            const size_t obase = ((size_t)(b * C + c + 2 * cp)) * nHW + h * nW + w;
            out[obase]       = o0;
            out[obase + nHW] = o1;
        }

        if (it < 15) {
            const int nb = cur ^ 1;
#pragma unroll
            for (int s = 0; s < 10; s++)
                if (xdi[s] >= 0) xib[nb * XI_BUF + xdi[s]] = xv[s];
            __syncthreads();
        }
        cur ^= 1;
    }
}

// ---------------------------------------------------------------------------
extern "C" void kernel_launch(void* const* d_in, const int* in_sizes, int n_in,
                              void* d_out, int out_size)
{
    (void)in_sizes; (void)n_in; (void)out_size;
    const float* x  = (const float*)d_in[0];
    const float* w1 = (const float*)d_in[1];
    const float* b1 = (const float*)d_in[2];
    const float* w2 = (const float*)d_in[3];
    const float* b2 = (const float*)d_in[4];
    float* out = (float*)d_out;

    cudaFuncSetAttribute(k1_conv1x1,
                         cudaFuncAttributeMaxDynamicSharedMemorySize, SM1_TOTAL);
    k0_transpose<<<64, 256>>>(w1);
    k1_conv1x1<<<512, 256, SM1_TOTAL>>>(x, b1);
    k2_encoder<<<dim3(4, 8, 8), 128>>>(w2, b2);
    k3_apply<<<dim3(4, 4, 32), 256>>>(x, out);
}

// round 14
// speedup vs baseline: 1.3669x; 1.2202x over previous
#include <cuda_runtime.h>
#include <cstdint>

typedef unsigned long long ull;

// Packed fp32x2 FMA (k2/k3)
#define FMA2(d, a, b, c) \
    asm("fma.rn.f32x2 %0, %1, %2, %3;" : "=l"(d) : "l"(a), "l"(b), "l"(c))
#define ADD2(d, a, b) \
    asm("add.rn.f32x2 %0, %1, %2;" : "=l"(d) : "l"(a), "l"(b))

__device__ __forceinline__ ull pack2(float lo, float hi) {
    ull r; asm("mov.b64 %0, {%1, %2};" : "=l"(r) : "f"(lo), "f"(hi)); return r;
}
__device__ __forceinline__ void unpack2(ull v, float& lo, float& hi) {
    asm("mov.b64 {%0, %1}, %2;" : "=f"(lo), "=f"(hi) : "l"(v));
}

__device__ __forceinline__ void cp_async16cg(void* smem_dst, const void* gsrc) {
    unsigned s = (unsigned)__cvta_generic_to_shared(smem_dst);
    asm volatile("cp.async.cg.shared.global [%0], [%1], 16;" :: "r"(s), "l"(gsrc));
}
#define CP_COMMIT()  asm volatile("cp.async.commit_group;")
#define CP_WAIT(n)   asm volatile("cp.async.wait_group %0;" :: "n"(n))

__device__ __forceinline__ uint32_t smem_u32(const void* p) {
    return (uint32_t)__cvta_generic_to_shared(p);
}

// mma.sync bf16 (sm_80 PTX — accepted by ptxas for sm_103)
#define MMA_BF16(d, a0, a1, a2, a3, b0, b1) \
    asm volatile("mma.sync.aligned.m16n8k16.row.col.f32.bf16.bf16.f32 " \
        "{%0,%1,%2,%3}, {%4,%5,%6,%7}, {%8,%9}, {%0,%1,%2,%3};" \
        : "+f"((d)[0]), "+f"((d)[1]), "+f"((d)[2]), "+f"((d)[3]) \
        : "r"(a0), "r"(a1), "r"(a2), "r"(a3), "r"(b0), "r"(b1))

#define LDSM_X4_T(r0, r1, r2, r3, addr) \
    asm volatile("ldmatrix.sync.aligned.m8n8.x4.trans.shared.b16 {%0,%1,%2,%3}, [%4];" \
        : "=r"(r0), "=r"(r1), "=r"(r2), "=r"(r3) : "r"(addr))

// pack two f32 -> bf16x2 (first src -> HIGH half)
#define CVT_BF2(d, hi_f, lo_f) \
    asm("cvt.rn.bf16x2.f32 %0, %1, %2;" : "=r"(d) : "f"(hi_f), "f"(lo_f))

// Problem constants
constexpr int B  = 8;
constexpr int C  = 256;
constexpr int M  = 64;
constexpr int H  = 128, W = 128, HW = H * W;
constexpr int KK = 25;
constexpr int nH = 64, nW = 64, nHW = nH * nW;

__device__ float g_mid[(size_t)B * M * HW];
__device__ float g_ker[(size_t)B * KK * nHW];

// ---------------------------------------------------------------------------
// Kernel 1 (tensor): 1x1 conv C=256->M=64 as bf16-split mma.sync GEMM.
// Block 64m x 256px, K=256 in 16 k16-chunks.  x: cp.async f32 staging into a
// 3-deep ring (WAR-safe: overwrite target last read 2 barriers ago) -> bf16
// hi/lo tiles (528B pitch).  w: LDG->split->48B-pitch A tiles.  3 MMA passes
// (hh, hl, lh); fp32 acc.  1 barrier/chunk.
// ---------------------------------------------------------------------------
constexpr int XST = 1040;                 // f32 stage row pitch (bytes)
constexpr int XBP = 528;                  // bf16 x row pitch
constexpr int APITCH = 48;                // A row pitch (16 bf16 + pad)
constexpr int STG_BUF = 16 * XST;         // 16640
constexpr int XB_BUF  = 16 * XBP;         // 8448
constexpr int A_BUF   = 64 * APITCH;      // 3072
constexpr int SM_STAGE = 0;                                // 3*16640 = 49920
constexpr int SM_XHI   = 49920;                            // 2*8448  = 16896
constexpr int SM_XLO   = 66816;                            // 16896
constexpr int SM_AHI   = 83712;                            // 2*3072  = 6144
constexpr int SM_ALO   = 89856;                            // 6144
constexpr int SM1_TOTAL = 96000;

__global__ void __launch_bounds__(256, 2) k1_conv1x1_tc(
    const float* __restrict__ x, const float* __restrict__ w1,
    const float* __restrict__ b1)
{
    extern __shared__ char sm[];
    const int t = threadIdx.x;
    const int w = t >> 5, l = t & 31;
    const int bx = blockIdx.x;            // 512
    const int b  = bx >> 6;
    const int p0 = (bx & 63) * 256;

    const float* xb = x + (size_t)(b * C) * HW + p0;

    // cp.async fill roles: row k_f, 4 granules
    const int k_f = t >> 4;
    const int c4  = t & 15;
    // convert roles: row k_c, 16 px starting pxq*16
    const int k_c = t & 15;
    const int pxq = t >> 4;
    // A fill roles
    const int m_a = t & 63;
    const int kq  = (t >> 6) * 4;         // k quad 0,4,8,12

    // ldmatrix B roles (fixed per thread)
    const int krole = (l & 7) + ((l >> 3) & 1) * 8;
    const int gbase = (w >> 2) * 16 + ((l >> 4) & 1);
    const uint32_t xh_u32 = smem_u32(sm + SM_XHI);
    const uint32_t xl_u32 = smem_u32(sm + SM_XLO);
    const uint32_t xoffb  = (uint32_t)(krole * XBP + gbase * 16);

    // A-frag read base
    const int mbase = (w & 3) * 16;
    const int arow  = (mbase + (l >> 2)) * APITCH + (l & 3) * 4;

    // ---- prologue: chunks 0,1 into stage ring slots 0,1 ----
#pragma unroll
    for (int j = 0; j < 4; j++)
        cp_async16cg(sm + SM_STAGE + k_f * XST + (c4 + j * 16) * 16,
                     xb + (size_t)k_f * HW + (c4 + j * 16) * 4);
    CP_COMMIT();
#pragma unroll
    for (int j = 0; j < 4; j++)
        cp_async16cg(sm + SM_STAGE + STG_BUF + k_f * XST + (c4 + j * 16) * 16,
                     xb + (size_t)(16 + k_f) * HW + (c4 + j * 16) * 4);
    CP_COMMIT();

    float4 wq = *(const float4*)&w1[m_a * C + kq];   // A chunk 0

    float acc[16][4];
#pragma unroll
    for (int i = 0; i < 16; i++)
#pragma unroll
        for (int j = 0; j < 4; j++) acc[i][j] = 0.f;

    CP_WAIT(1);
    __syncthreads();

    // convert chunk 0 (x + A) into bf[0], prefetch A chunk 1
    {
        const char* st = sm + SM_STAGE;           // ring slot 0
        char* xh = sm + SM_XHI;
        char* xl = sm + SM_XLO;
        uint32_t hi[8], lo[8];
#pragma unroll
        for (int q = 0; q < 4; q++) {
            float4 v = *(const float4*)(st + k_c * XST + pxq * 64 + q * 16);
            CVT_BF2(hi[2*q],   v.y, v.x);
            CVT_BF2(hi[2*q+1], v.w, v.z);
            float l0 = v.x - __uint_as_float(hi[2*q] << 16);
            float l1 = v.y - __uint_as_float(hi[2*q] & 0xFFFF0000u);
            float l2 = v.z - __uint_as_float(hi[2*q+1] << 16);
            float l3 = v.w - __uint_as_float(hi[2*q+1] & 0xFFFF0000u);
            CVT_BF2(lo[2*q],   l1, l0);
            CVT_BF2(lo[2*q+1], l3, l2);
        }
        *(uint4*)(xh + k_c * XBP + pxq * 32)      = make_uint4(hi[0],hi[1],hi[2],hi[3]);
        *(uint4*)(xh + k_c * XBP + pxq * 32 + 16) = make_uint4(hi[4],hi[5],hi[6],hi[7]);
        *(uint4*)(xl + k_c * XBP + pxq * 32)      = make_uint4(lo[0],lo[1],lo[2],lo[3]);
        *(uint4*)(xl + k_c * XBP + pxq * 32 + 16) = make_uint4(lo[4],lo[5],lo[6],lo[7]);
        uint32_t h0, h1, l0p, l1p;
        CVT_BF2(h0, wq.y, wq.x); CVT_BF2(h1, wq.w, wq.z);
        float a0 = wq.x - __uint_as_float(h0 << 16);
        float a1 = wq.y - __uint_as_float(h0 & 0xFFFF0000u);
        float a2 = wq.z - __uint_as_float(h1 << 16);
        float a3 = wq.w - __uint_as_float(h1 & 0xFFFF0000u);
        CVT_BF2(l0p, a1, a0); CVT_BF2(l1p, a3, a2);
        *(uint2*)(sm + SM_AHI + m_a * APITCH + kq * 2) = make_uint2(h0, h1);
        *(uint2*)(sm + SM_ALO + m_a * APITCH + kq * 2) = make_uint2(l0p, l1p);
        wq = *(const float4*)&w1[m_a * C + 16 + kq];
    }

#pragma unroll 1
    for (int ch = 0; ch < 16; ch++) {
        const int cb = ch & 1, nb = cb ^ 1;
        // issue chunk ch+2 into ring slot (ch+2)%3: that slot's last reader
        // (convert of chunk ch-1) finished before the PREVIOUS barrier.
        if (ch < 14) {
            char* dst = sm + SM_STAGE + ((ch + 2) % 3) * STG_BUF;
#pragma unroll
            for (int j = 0; j < 4; j++)
                cp_async16cg(dst + k_f * XST + (c4 + j * 16) * 16,
                             xb + (size_t)((ch + 2) * 16 + k_f) * HW + (c4 + j * 16) * 4);
            CP_COMMIT();
            CP_WAIT(1);
        } else {
            CP_WAIT(0);
        }
        __syncthreads();   // chunk ch+1 stage visible; bf[nb] free; bf[cb] sealed

        // convert chunk ch+1 from ring slot (ch+1)%3 into bf[nb]
        if (ch < 15) {
            const char* st = sm + SM_STAGE + ((ch + 1) % 3) * STG_BUF;
            char* xh = sm + SM_XHI + nb * XB_BUF;
            char* xl = sm + SM_XLO + nb * XB_BUF;
            uint32_t hi[8], lo[8];
#pragma unroll
            for (int q = 0; q < 4; q++) {
                float4 v = *(const float4*)(st + k_c * XST + pxq * 64 + q * 16);
                CVT_BF2(hi[2*q],   v.y, v.x);
                CVT_BF2(hi[2*q+1], v.w, v.z);
                float l0 = v.x - __uint_as_float(hi[2*q] << 16);
                float l1 = v.y - __uint_as_float(hi[2*q] & 0xFFFF0000u);
                float l2 = v.z - __uint_as_float(hi[2*q+1] << 16);
                float l3 = v.w - __uint_as_float(hi[2*q+1] & 0xFFFF0000u);
                CVT_BF2(lo[2*q],   l1, l0);
                CVT_BF2(lo[2*q+1], l3, l2);
            }
            *(uint4*)(xh + k_c * XBP + pxq * 32)      = make_uint4(hi[0],hi[1],hi[2],hi[3]);
            *(uint4*)(xh + k_c * XBP + pxq * 32 + 16) = make_uint4(hi[4],hi[5],hi[6],hi[7]);
            *(uint4*)(xl + k_c * XBP + pxq * 32)      = make_uint4(lo[0],lo[1],lo[2],lo[3]);
            *(uint4*)(xl + k_c * XBP + pxq * 32 + 16) = make_uint4(lo[4],lo[5],lo[6],lo[7]);
            uint32_t h0, h1, l0p, l1p;
            CVT_BF2(h0, wq.y, wq.x); CVT_BF2(h1, wq.w, wq.z);
            float a0 = wq.x - __uint_as_float(h0 << 16);
            float a1 = wq.y - __uint_as_float(h0 & 0xFFFF0000u);
            float a2 = wq.z - __uint_as_float(h1 << 16);
            float a3 = wq.w - __uint_as_float(h1 & 0xFFFF0000u);
            CVT_BF2(l0p, a1, a0); CVT_BF2(l1p, a3, a2);
            *(uint2*)(sm + SM_AHI + nb * A_BUF + m_a * APITCH + kq * 2) = make_uint2(h0, h1);
            *(uint2*)(sm + SM_ALO + nb * A_BUF + m_a * APITCH + kq * 2) = make_uint2(l0p, l1p);
            if (ch < 14)
                wq = *(const float4*)&w1[m_a * C + (ch + 2) * 16 + kq];
        }

        // compute chunk ch from bf[cb]
        {
            const char* ah = sm + SM_AHI + cb * A_BUF;
            const char* al = sm + SM_ALO + cb * A_BUF;
            uint32_t a_h0 = *(const uint32_t*)(ah + arow);
            uint32_t a_h1 = *(const uint32_t*)(ah + arow + 8 * APITCH);
            uint32_t a_h2 = *(const uint32_t*)(ah + arow + 16);
            uint32_t a_h3 = *(const uint32_t*)(ah + arow + 8 * APITCH + 16);
            uint32_t a_l0 = *(const uint32_t*)(al + arow);
            uint32_t a_l1 = *(const uint32_t*)(al + arow + 8 * APITCH);
            uint32_t a_l2 = *(const uint32_t*)(al + arow + 16);
            uint32_t a_l3 = *(const uint32_t*)(al + arow + 8 * APITCH + 16);
            const uint32_t xh_b = xh_u32 + cb * XB_BUF + xoffb;
            const uint32_t xl_b = xl_u32 + cb * XB_BUF + xoffb;
#pragma unroll
            for (int np = 0; np < 8; np++) {
                uint32_t bh0, bh1, bh2, bh3, bl0, bl1, bl2, bl3;
                LDSM_X4_T(bh0, bh1, bh2, bh3, xh_b + np * 32);
                LDSM_X4_T(bl0, bl1, bl2, bl3, xl_b + np * 32);
                MMA_BF16(acc[2*np],   a_h0, a_h1, a_h2, a_h3, bh0, bh1);
                MMA_BF16(acc[2*np],   a_h0, a_h1, a_h2, a_h3, bl0, bl1);
                MMA_BF16(acc[2*np],   a_l0, a_l1, a_l2, a_l3, bh0, bh1);
                MMA_BF16(acc[2*np+1], a_h0, a_h1, a_h2, a_h3, bh2, bh3);
                MMA_BF16(acc[2*np+1], a_h0, a_h1, a_h2, a_h3, bl2, bl3);
                MMA_BF16(acc[2*np+1], a_l0, a_l1, a_l2, a_l3, bh2, bh3);
            }
        }
    }

    // ---- epilogue: bias + store ----
    const int m1 = mbase + (l >> 2);
    const int m2 = m1 + 8;
    const float bias1 = b1[m1], bias2 = b1[m2];
    const int pxb = (w >> 2) * 128 + (l & 3) * 2;
    float* o1 = g_mid + (size_t)(b * M + m1) * HW + p0 + pxb;
    float* o2 = g_mid + (size_t)(b * M + m2) * HW + p0 + pxb;
#pragma unroll
    for (int nt = 0; nt < 16; nt++) {
        *(float2*)(o1 + nt * 8) = make_float2(acc[nt][0] + bias1, acc[nt][1] + bias1);
        *(float2*)(o2 + nt * 8) = make_float2(acc[nt][2] + bias2, acc[nt][3] + bias2);
    }
}

// ---------------------------------------------------------------------------
// Kernel 2: 3x3 conv s2 p1, 64->25, + bias + softmax (R7-proven, verbatim).
// ---------------------------------------------------------------------------
__global__ void __launch_bounds__(128) k2_encoder(
    const float* __restrict__ w2, const float* __restrict__ b2)
{
    __shared__ float2 ms[2][2][17][37];
    __shared__ float2 ws[2][2][9][26];

    const int t  = threadIdx.x;
    const int b  = blockIdx.z;
    const int h0 = blockIdx.y * 8;
    const int w0 = blockIdx.x * 16;
    const int ty = t >> 4;
    const int tx = t & 15;

    constexpr int MS_BUF = 2 * 17 * 37;
    constexpr int WS_BUF = 2 * 9 * 26;
    float2* msb = &ms[0][0][0][0];
    float2* wsb = &ws[0][0][0][0];

    int ms_off[9], ms_di[9];
#pragma unroll
    for (int s = 0; s < 9; s++) {
        int idx = t + s * 128;
        ms_off[s] = -1; ms_di[s] = -1;
        if (idx < 1122) {
            int cp = idx / 561, r = idx % 561;
            int i = r / 33, jj = r % 33;
            int ih = 2 * h0 - 1 + i, iw = 2 * w0 - 1 + jj;
            ms_di[s] = (cp * 17 + i) * 37 + jj;
            if ((unsigned)ih < 128u && (unsigned)iw < 128u)
                ms_off[s] = (b * M + 2 * cp) * HW + ih * W + iw;
        }
    }
    int ws_src[4], ws_di[4];
#pragma unroll
    for (int s = 0; s < 4; s++) {
        int idx = t + s * 128;
        ws_src[s] = -1; ws_di[s] = -1;
        if (idx < 450) {
            int cp = idx / 225, r = idx % 225;
            int j = r / 25, k = r % 25;
            ws_src[s] = (k * M + 2 * cp) * 9 + j;
            ws_di[s] = (cp * 9 + j) * 26 + k;
        }
    }

    float2 mv[9], wvv[4];
#pragma unroll
    for (int s = 0; s < 9; s++) {
        mv[s] = make_float2(0.f, 0.f);
        if (ms_off[s] >= 0) {
            mv[s].x = g_mid[ms_off[s]];
            mv[s].y = g_mid[ms_off[s] + HW];
        }
    }
#pragma unroll
    for (int s = 0; s < 4; s++)
        if (ws_src[s] >= 0)
            wvv[s] = make_float2(w2[ws_src[s]], w2[ws_src[s] + 9]);
#pragma unroll
    for (int s = 0; s < 9; s++) if (ms_di[s] >= 0) msb[ms_di[s]] = mv[s];
#pragma unroll
    for (int s = 0; s < 4; s++) if (ws_di[s] >= 0) wsb[ws_di[s]] = wvv[s];
    __syncthreads();

    ull acc[25];
#pragma unroll
    for (int k = 0; k < 25; k++) acc[k] = 0ULL;

    int cur = 0;
#pragma unroll 1
    for (int chk = 0; chk < 16; chk++) {
        if (chk < 15) {
            const int moff = (chk + 1) * 4 * HW;
#pragma unroll
            for (int s = 0; s < 9; s++) {
                mv[s] = make_float2(0.f, 0.f);
                if (ms_off[s] >= 0) {
                    mv[s].x = g_mid[ms_off[s] + moff];
                    mv[s].y = g_mid[ms_off[s] + moff + HW];
                }
            }
            const int woff = (chk + 1) * 36;
#pragma unroll
            for (int s = 0; s < 4; s++)
                if (ws_src[s] >= 0)
                    wvv[s] = make_float2(w2[ws_src[s] + woff],
                                         w2[ws_src[s] + woff + 9]);
        }

#pragma unroll
        for (int cp = 0; cp < 2; cp++) {
            ull xp[9];
#pragma unroll
            for (int i = 0; i < 3; i++)
#pragma unroll
                for (int j = 0; j < 3; j++)
                    xp[i * 3 + j] = *(const ull*)&ms[cur][cp][2 * ty + i][2 * tx + j];
#pragma unroll
            for (int j9 = 0; j9 < 9; j9++) {
#pragma unroll
                for (int k2 = 0; k2 < 12; k2++) {
                    ulonglong2 wq = *(const ulonglong2*)&ws[cur][cp][j9][2 * k2];
                    FMA2(acc[2*k2  ], wq.x, xp[j9], acc[2*k2  ]);
                    FMA2(acc[2*k2+1], wq.y, xp[j9], acc[2*k2+1]);
                }
                ull wl = *(const ull*)&ws[cur][cp][j9][24];
                FMA2(acc[24], wl, xp[j9], acc[24]);
            }
        }

        if (chk < 15) {
            const int nb = cur ^ 1;
#pragma unroll
            for (int s = 0; s < 9; s++)
                if (ms_di[s] >= 0) msb[nb * MS_BUF + ms_di[s]] = mv[s];
#pragma unroll
            for (int s = 0; s < 4; s++)
                if (ws_di[s] >= 0) wsb[nb * WS_BUF + ws_di[s]] = wvv[s];
            __syncthreads();
        }
        cur ^= 1;
    }

    float lg[25];
#pragma unroll
    for (int k = 0; k < 25; k++) {
        float a, bq; unpack2(acc[k], a, bq);
        lg[k] = a + bq + b2[k];
    }
    float mx = lg[0];
#pragma unroll
    for (int k = 1; k < 25; k++) mx = fmaxf(mx, lg[k]);
    float e[25], sum = 0.f;
#pragma unroll
    for (int k = 0; k < 25; k++) { e[k] = __expf(lg[k] - mx); sum += e[k]; }
    const float inv = 1.f / sum;
    const int h = h0 + ty, w = w0 + tx;
    const size_t base = ((size_t)b * KK) * nHW + h * nW + w;
#pragma unroll
    for (int k = 0; k < 25; k++)
        g_ker[base + (size_t)k * nHW] = e[k] * inv;
}

// ---------------------------------------------------------------------------
// Kernel 3: softmax-weighted 5x5 window sum (R7-proven, verbatim).
// ---------------------------------------------------------------------------
__global__ void __launch_bounds__(256) k3_apply(
    const float* __restrict__ x, float* __restrict__ out)
{
    __shared__ float2 xi[2][2][35][38];

    const int t  = threadIdx.x;
    const int bz = blockIdx.z;
    const int b  = bz >> 2;
    const int cbase = (bz & 3) * 64;
    const int h0 = blockIdx.y * 16, w0 = blockIdx.x * 16;
    const int py = t >> 4, px = t & 15;
    const int h = h0 + py, w = w0 + px;

    constexpr int XI_BUF = 2 * 35 * 38;
    float2* xib = &xi[0][0][0][0];

    ull kp[25];
#pragma unroll
    for (int k = 0; k < 25; k++) {
        float kv = g_ker[((size_t)(b * KK + k)) * nHW + h * nW + w];
        kp[k] = pack2(kv, kv);
    }

    const int ir0 = 2 * h0 - 2, ic0 = 2 * w0 - 2;
    const float* xb = x + ((size_t)(b * C + cbase)) * HW;

    int xoff[10], xdi[10];
#pragma unroll
    for (int s = 0; s < 10; s++) {
        int idx = t + s * 256;
        xoff[s] = -1; xdi[s] = -1;
        if (idx < 2450) {
            int cp = (idx >= 1225) ? 1 : 0;
            int rr = idx - cp * 1225;
            int r = rr / 35, cc = rr - r * 35;
            int ir = ir0 + r, ic = ic0 + cc;
            xdi[s] = (cp * 35 + r) * 38 + cc;
            if ((unsigned)ir < 128u && (unsigned)ic < 128u)
                xoff[s] = cp * 2 * HW + ir * W + ic;
        }
    }

    float2 xv[10];
#pragma unroll
    for (int s = 0; s < 10; s++) {
        xv[s] = make_float2(0.f, 0.f);
        if (xoff[s] >= 0) {
            xv[s].x = xb[xoff[s]];
            xv[s].y = xb[xoff[s] + HW];
        }
    }
#pragma unroll
    for (int s = 0; s < 10; s++) if (xdi[s] >= 0) xib[xdi[s]] = xv[s];
    __syncthreads();

    int cur = 0;
#pragma unroll 1
    for (int it = 0; it < 16; it++) {
        if (it < 15) {
            const int coff = (it + 1) * 4 * HW;
#pragma unroll
            for (int s = 0; s < 10; s++) {
                xv[s] = make_float2(0.f, 0.f);
                if (xoff[s] >= 0) {
                    xv[s].x = xb[xoff[s] + coff];
                    xv[s].y = xb[xoff[s] + coff + HW];
                }
            }
        }

        const int c = cbase + it * 4;
#pragma unroll
        for (int cp = 0; cp < 2; cp++) {
            ull a[5];
#pragma unroll
            for (int i = 0; i < 5; i++) a[i] = 0ULL;
#pragma unroll
            for (int i = 0; i < 5; i++)
#pragma unroll
                for (int j = 0; j < 5; j++) {
                    ull xvv = *(const ull*)&xi[cur][cp][2 * py + i][2 * px + j];
                    const int k = i * 5 + j;
                    FMA2(a[k % 5], kp[k], xvv, a[k % 5]);
                }
            ull s01, s23, ssum;
            ADD2(s01, a[0], a[1]);
            ADD2(s23, a[2], a[3]);
            ADD2(s01, s01, s23);
            ADD2(ssum, s01, a[4]);
            float o0, o1; unpack2(ssum, o0, o1);
            const size_t obase = ((size_t)(b * C + c + 2 * cp)) * nHW + h * nW + w;
            out[obase]       = o0;
            out[obase + nHW] = o1;
        }

        if (it < 15) {
            const int nb = cur ^ 1;
#pragma unroll
            for (int s = 0; s < 10; s++)
                if (xdi[s] >= 0) xib[nb * XI_BUF + xdi[s]] = xv[s];
            __syncthreads();
        }
        cur ^= 1;
    }
}

// ---------------------------------------------------------------------------
extern "C" void kernel_launch(void* const* d_in, const int* in_sizes, int n_in,
                              void* d_out, int out_size)
{
    (void)in_sizes; (void)n_in; (void)out_size;
    const float* x  = (const float*)d_in[0];
    const float* w1 = (const float*)d_in[1];
    const float* b1 = (const float*)d_in[2];
    const float* w2 = (const float*)d_in[3];
    const float* b2 = (const float*)d_in[4];
    float* out = (float*)d_out;

    cudaFuncSetAttribute(k1_conv1x1_tc,
                         cudaFuncAttributeMaxDynamicSharedMemorySize, SM1_TOTAL);
    k1_conv1x1_tc<<<512, 256, SM1_TOTAL>>>(x, w1, b1);
    k2_encoder<<<dim3(4, 8, 8), 128>>>(w2, b2);
    k3_apply<<<dim3(4, 4, 32), 256>>>(x, out);
}

// round 15
// speedup vs baseline: 1.3814x; 1.0106x over previous
#include <cuda_runtime.h>
#include <cstdint>

typedef unsigned long long ull;

// Packed fp32x2 FMA (k2/k3)
#define FMA2(d, a, b, c) \
    asm("fma.rn.f32x2 %0, %1, %2, %3;" : "=l"(d) : "l"(a), "l"(b), "l"(c))
#define ADD2(d, a, b) \
    asm("add.rn.f32x2 %0, %1, %2;" : "=l"(d) : "l"(a), "l"(b))

__device__ __forceinline__ ull pack2(float lo, float hi) {
    ull r; asm("mov.b64 %0, {%1, %2};" : "=l"(r) : "f"(lo), "f"(hi)); return r;
}
__device__ __forceinline__ void unpack2(ull v, float& lo, float& hi) {
    asm("mov.b64 {%0, %1}, %2;" : "=f"(lo), "=f"(hi) : "l"(v));
}

__device__ __forceinline__ uint32_t smem_u32(const void* p) {
    return (uint32_t)__cvta_generic_to_shared(p);
}

// mma.sync bf16 (sm_80 PTX — accepted by ptxas for sm_103)
#define MMA_BF16(d, a0, a1, a2, a3, b0, b1) \
    asm volatile("mma.sync.aligned.m16n8k16.row.col.f32.bf16.bf16.f32 " \
        "{%0,%1,%2,%3}, {%4,%5,%6,%7}, {%8,%9}, {%0,%1,%2,%3};" \
        : "+f"((d)[0]), "+f"((d)[1]), "+f"((d)[2]), "+f"((d)[3]) \
        : "r"(a0), "r"(a1), "r"(a2), "r"(a3), "r"(b0), "r"(b1))

#define LDSM_X4_T(r0, r1, r2, r3, addr) \
    asm volatile("ldmatrix.sync.aligned.m8n8.x4.trans.shared.b16 {%0,%1,%2,%3}, [%4];" \
        : "=r"(r0), "=r"(r1), "=r"(r2), "=r"(r3) : "r"(addr))

// pack two f32 -> bf16x2 (first src -> HIGH half)
#define CVT_BF2(d, hi_f, lo_f) \
    asm("cvt.rn.bf16x2.f32 %0, %1, %2;" : "=r"(d) : "f"(hi_f), "f"(lo_f))

// Problem constants
constexpr int B  = 8;
constexpr int C  = 256;
constexpr int M  = 64;
constexpr int H  = 128, W = 128, HW = H * W;
constexpr int KK = 25;
constexpr int nH = 64, nW = 64, nHW = nH * nW;

__device__ float g_mid[(size_t)B * M * HW];
__device__ float g_ker[(size_t)B * KK * nHW];

// ---------------------------------------------------------------------------
// Kernel 1 (tensor): 1x1 conv C=256->M=64 as bf16-split mma.sync GEMM.
// Block 64m x 256px, K=256 in 16 k16-chunks.  NO f32 staging: x chunk ch+1
// is LDG'd into registers before the MMA section (latency hidden under
// compute), converted in regs, STS'd as bf16 hi/lo (528B pitch).
// w: LDG->split->48B-pitch A tiles.  3 MMA passes (hh, hl, lh).
// 1 barrier/chunk.  Static smem = 46 KB.
// ---------------------------------------------------------------------------
constexpr int XBP = 528;                  // bf16 x row pitch
constexpr int APITCH = 48;                // A row pitch (16 bf16 + pad)
constexpr int XB_BUF  = 16 * XBP;         // 8448
constexpr int A_BUF   = 64 * APITCH;      // 3072

__global__ void __launch_bounds__(256, 2) k1_conv1x1_tc(
    const float* __restrict__ x, const float* __restrict__ w1,
    const float* __restrict__ b1)
{
    __shared__ char s_xhi[2 * XB_BUF];
    __shared__ char s_xlo[2 * XB_BUF];
    __shared__ char s_ahi[2 * A_BUF];
    __shared__ char s_alo[2 * A_BUF];

    const int t = threadIdx.x;
    const int w = t >> 5, l = t & 31;
    const int bx = blockIdx.x;            // 512
    const int b  = bx >> 6;
    const int p0 = (bx & 63) * 256;

    const float* xb = x + (size_t)(b * C) * HW + p0;

    // x load/convert roles: row k_f, 4 groups of 4 px at (c4 + j*16)*4
    const int k_f = t >> 4;
    const int c4  = t & 15;
    // A fill roles
    const int m_a = t & 63;
    const int kq  = (t >> 6) * 4;         // k quad 0,4,8,12

    // ldmatrix B roles (fixed per thread)
    const int krole = (l & 7) + ((l >> 3) & 1) * 8;
    const int gbase = (w >> 2) * 16 + ((l >> 4) & 1);
    const uint32_t xh_u32 = smem_u32(s_xhi);
    const uint32_t xl_u32 = smem_u32(s_xlo);
    const uint32_t xoffb  = (uint32_t)(krole * XBP + gbase * 16);

    // A-frag read base
    const int mbase = (w & 3) * 16;
    const int arow  = (mbase + (l >> 2)) * APITCH + (l & 3) * 4;

    // x-STS byte offsets for the 4 groups: px (c4+j*16)*4 -> bytes c4*8+j*128
    const int xsts = k_f * XBP + c4 * 8;

    float4 xr[4];
    float4 wq;

    // ---- prologue: chunk 0 ----
#pragma unroll
    for (int j = 0; j < 4; j++)
        xr[j] = *(const float4*)(xb + (size_t)k_f * HW + (c4 + j * 16) * 4);
    wq = *(const float4*)&w1[m_a * C + kq];

    {
        char* xh = s_xhi;
        char* xl = s_xlo;
#pragma unroll
        for (int j = 0; j < 4; j++) {
            float4 v = xr[j];
            uint32_t h0, h1, lo0, lo1;
            CVT_BF2(h0, v.y, v.x);
            CVT_BF2(h1, v.w, v.z);
            float l0 = v.x - __uint_as_float(h0 << 16);
            float l1 = v.y - __uint_as_float(h0 & 0xFFFF0000u);
            float l2 = v.z - __uint_as_float(h1 << 16);
            float l3 = v.w - __uint_as_float(h1 & 0xFFFF0000u);
            CVT_BF2(lo0, l1, l0);
            CVT_BF2(lo1, l3, l2);
            *(uint2*)(xh + xsts + j * 128) = make_uint2(h0, h1);
            *(uint2*)(xl + xsts + j * 128) = make_uint2(lo0, lo1);
        }
        uint32_t h0, h1, l0p, l1p;
        CVT_BF2(h0, wq.y, wq.x); CVT_BF2(h1, wq.w, wq.z);
        float a0 = wq.x - __uint_as_float(h0 << 16);
        float a1 = wq.y - __uint_as_float(h0 & 0xFFFF0000u);
        float a2 = wq.z - __uint_as_float(h1 << 16);
        float a3 = wq.w - __uint_as_float(h1 & 0xFFFF0000u);
        CVT_BF2(l0p, a1, a0); CVT_BF2(l1p, a3, a2);
        *(uint2*)(s_ahi + m_a * APITCH + kq * 2) = make_uint2(h0, h1);
        *(uint2*)(s_alo + m_a * APITCH + kq * 2) = make_uint2(l0p, l1p);
        wq = *(const float4*)&w1[m_a * C + 16 + kq];
    }

    float acc[16][4];
#pragma unroll
    for (int i = 0; i < 16; i++)
#pragma unroll
        for (int j = 0; j < 4; j++) acc[i][j] = 0.f;

    __syncthreads();

#pragma unroll 1
    for (int ch = 0; ch < 16; ch++) {
        const int cb = ch & 1, nb = cb ^ 1;

        // issue LDGs for chunk ch+1 (latency hidden under the MMA section)
        if (ch < 15) {
#pragma unroll
            for (int j = 0; j < 4; j++)
                xr[j] = *(const float4*)(xb + (size_t)((ch + 1) * 16 + k_f) * HW
                                         + (c4 + j * 16) * 4);
        }

        // compute chunk ch from bf[cb]
        {
            const char* ah = s_ahi + cb * A_BUF;
            const char* al = s_alo + cb * A_BUF;
            uint32_t a_h0 = *(const uint32_t*)(ah + arow);
            uint32_t a_h1 = *(const uint32_t*)(ah + arow + 8 * APITCH);
            uint32_t a_h2 = *(const uint32_t*)(ah + arow + 16);
            uint32_t a_h3 = *(const uint32_t*)(ah + arow + 8 * APITCH + 16);
            uint32_t a_l0 = *(const uint32_t*)(al + arow);
            uint32_t a_l1 = *(const uint32_t*)(al + arow + 8 * APITCH);
            uint32_t a_l2 = *(const uint32_t*)(al + arow + 16);
            uint32_t a_l3 = *(const uint32_t*)(al + arow + 8 * APITCH + 16);
            const uint32_t xh_b = xh_u32 + cb * XB_BUF + xoffb;
            const uint32_t xl_b = xl_u32 + cb * XB_BUF + xoffb;
#pragma unroll
            for (int np = 0; np < 8; np++) {
                uint32_t bh0, bh1, bh2, bh3, bl0, bl1, bl2, bl3;
                LDSM_X4_T(bh0, bh1, bh2, bh3, xh_b + np * 32);
                LDSM_X4_T(bl0, bl1, bl2, bl3, xl_b + np * 32);
                MMA_BF16(acc[2*np],   a_h0, a_h1, a_h2, a_h3, bh0, bh1);
                MMA_BF16(acc[2*np],   a_h0, a_h1, a_h2, a_h3, bl0, bl1);
                MMA_BF16(acc[2*np],   a_l0, a_l1, a_l2, a_l3, bh0, bh1);
                MMA_BF16(acc[2*np+1], a_h0, a_h1, a_h2, a_h3, bh2, bh3);
                MMA_BF16(acc[2*np+1], a_h0, a_h1, a_h2, a_h3, bl2, bl3);
                MMA_BF16(acc[2*np+1], a_l0, a_l1, a_l2, a_l3, bh2, bh3);
            }
        }

        // convert chunk ch+1 -> bf[nb] (LDG data arrived during compute)
        if (ch < 15) {
            char* xh = s_xhi + nb * XB_BUF;
            char* xl = s_xlo + nb * XB_BUF;
#pragma unroll
            for (int j = 0; j < 4; j++) {
                float4 v = xr[j];
                uint32_t h0, h1, lo0, lo1;
                CVT_BF2(h0, v.y, v.x);
                CVT_BF2(h1, v.w, v.z);
                float l0 = v.x - __uint_as_float(h0 << 16);
                float l1 = v.y - __uint_as_float(h0 & 0xFFFF0000u);
                float l2 = v.z - __uint_as_float(h1 << 16);
                float l3 = v.w - __uint_as_float(h1 & 0xFFFF0000u);
                CVT_BF2(lo0, l1, l0);
                CVT_BF2(lo1, l3, l2);
                *(uint2*)(xh + xsts + j * 128) = make_uint2(h0, h1);
                *(uint2*)(xl + xsts + j * 128) = make_uint2(lo0, lo1);
            }
            uint32_t h0, h1, l0p, l1p;
            CVT_BF2(h0, wq.y, wq.x); CVT_BF2(h1, wq.w, wq.z);
            float a0 = wq.x - __uint_as_float(h0 << 16);
            float a1 = wq.y - __uint_as_float(h0 & 0xFFFF0000u);
            float a2 = wq.z - __uint_as_float(h1 << 16);
            float a3 = wq.w - __uint_as_float(h1 & 0xFFFF0000u);
            CVT_BF2(l0p, a1, a0); CVT_BF2(l1p, a3, a2);
            *(uint2*)(s_ahi + nb * A_BUF + m_a * APITCH + kq * 2) = make_uint2(h0, h1);
            *(uint2*)(s_alo + nb * A_BUF + m_a * APITCH + kq * 2) = make_uint2(l0p, l1p);
            if (ch < 14)
                wq = *(const float4*)&w1[m_a * C + (ch + 2) * 16 + kq];
        }
        __syncthreads();
    }

    // ---- epilogue: bias + store ----
    const int m1 = mbase + (l >> 2);
    const int m2 = m1 + 8;
    const float bias1 = b1[m1], bias2 = b1[m2];
    const int pxb = (w >> 2) * 128 + (l & 3) * 2;
    float* o1 = g_mid + (size_t)(b * M + m1) * HW + p0 + pxb;
    float* o2 = g_mid + (size_t)(b * M + m2) * HW + p0 + pxb;
#pragma unroll
    for (int nt = 0; nt < 16; nt++) {
        *(float2*)(o1 + nt * 8) = make_float2(acc[nt][0] + bias1, acc[nt][1] + bias1);
        *(float2*)(o2 + nt * 8) = make_float2(acc[nt][2] + bias2, acc[nt][3] + bias2);
    }
}

// ---------------------------------------------------------------------------
// Kernel 2: 3x3 conv s2 p1, 64->25, + bias + softmax (R7-proven, verbatim).
// ---------------------------------------------------------------------------
__global__ void __launch_bounds__(128) k2_encoder(
    const float* __restrict__ w2, const float* __restrict__ b2)
{
    __shared__ float2 ms[2][2][17][37];
    __shared__ float2 ws[2][2][9][26];

    const int t  = threadIdx.x;
    const int b  = blockIdx.z;
    const int h0 = blockIdx.y * 8;
    const int w0 = blockIdx.x * 16;
    const int ty = t >> 4;
    const int tx = t & 15;

    constexpr int MS_BUF = 2 * 17 * 37;
    constexpr int WS_BUF = 2 * 9 * 26;
    float2* msb = &ms[0][0][0][0];
    float2* wsb = &ws[0][0][0][0];

    int ms_off[9], ms_di[9];
#pragma unroll
    for (int s = 0; s < 9; s++) {
        int idx = t + s * 128;
        ms_off[s] = -1; ms_di[s] = -1;
        if (idx < 1122) {
            int cp = idx / 561, r = idx % 561;
            int i = r / 33, jj = r % 33;
            int ih = 2 * h0 - 1 + i, iw = 2 * w0 - 1 + jj;
            ms_di[s] = (cp * 17 + i) * 37 + jj;
            if ((unsigned)ih < 128u && (unsigned)iw < 128u)
                ms_off[s] = (b * M + 2 * cp) * HW + ih * W + iw;
        }
    }
    int ws_src[4], ws_di[4];
#pragma unroll
    for (int s = 0; s < 4; s++) {
        int idx = t + s * 128;
        ws_src[s] = -1; ws_di[s] = -1;
        if (idx < 450) {
            int cp = idx / 225, r = idx % 225;
            int j = r / 25, k = r % 25;
            ws_src[s] = (k * M + 2 * cp) * 9 + j;
            ws_di[s] = (cp * 9 + j) * 26 + k;
        }
    }

    float2 mv[9], wvv[4];
#pragma unroll
    for (int s = 0; s < 9; s++) {
        mv[s] = make_float2(0.f, 0.f);
        if (ms_off[s] >= 0) {
            mv[s].x = g_mid[ms_off[s]];
            mv[s].y = g_mid[ms_off[s] + HW];
        }
    }
#pragma unroll
    for (int s = 0; s < 4; s++)
        if (ws_src[s] >= 0)
            wvv[s] = make_float2(w2[ws_src[s]], w2[ws_src[s] + 9]);
#pragma unroll
    for (int s = 0; s < 9; s++) if (ms_di[s] >= 0) msb[ms_di[s]] = mv[s];
#pragma unroll
    for (int s = 0; s < 4; s++) if (ws_di[s] >= 0) wsb[ws_di[s]] = wvv[s];
    __syncthreads();

    ull acc[25];
#pragma unroll
    for (int k = 0; k < 25; k++) acc[k] = 0ULL;

    int cur = 0;
#pragma unroll 1
    for (int chk = 0; chk < 16; chk++) {
        if (chk < 15) {
            const int moff = (chk + 1) * 4 * HW;
#pragma unroll
            for (int s = 0; s < 9; s++) {
                mv[s] = make_float2(0.f, 0.f);
                if (ms_off[s] >= 0) {
                    mv[s].x = g_mid[ms_off[s] + moff];
                    mv[s].y = g_mid[ms_off[s] + moff + HW];
                }
            }
            const int woff = (chk + 1) * 36;
#pragma unroll
            for (int s = 0; s < 4; s++)
                if (ws_src[s] >= 0)
                    wvv[s] = make_float2(w2[ws_src[s] + woff],
                                         w2[ws_src[s] + woff + 9]);
        }

#pragma unroll
        for (int cp = 0; cp < 2; cp++) {
            ull xp[9];
#pragma unroll
            for (int i = 0; i < 3; i++)
#pragma unroll
                for (int j = 0; j < 3; j++)
                    xp[i * 3 + j] = *(const ull*)&ms[cur][cp][2 * ty + i][2 * tx + j];
#pragma unroll
            for (int j9 = 0; j9 < 9; j9++) {
#pragma unroll
                for (int k2 = 0; k2 < 12; k2++) {
                    ulonglong2 wq = *(const ulonglong2*)&ws[cur][cp][j9][2 * k2];
                    FMA2(acc[2*k2  ], wq.x, xp[j9], acc[2*k2  ]);
                    FMA2(acc[2*k2+1], wq.y, xp[j9], acc[2*k2+1]);
                }
                ull wl = *(const ull*)&ws[cur][cp][j9][24];
                FMA2(acc[24], wl, xp[j9], acc[24]);
            }
        }

        if (chk < 15) {
            const int nb = cur ^ 1;
#pragma unroll
            for (int s = 0; s < 9; s++)
                if (ms_di[s] >= 0) msb[nb * MS_BUF + ms_di[s]] = mv[s];
#pragma unroll
            for (int s = 0; s < 4; s++)
                if (ws_di[s] >= 0) wsb[nb * WS_BUF + ws_di[s]] = wvv[s];
            __syncthreads();
        }
        cur ^= 1;
    }

    float lg[25];
#pragma unroll
    for (int k = 0; k < 25; k++) {
        float a, bq; unpack2(acc[k], a, bq);
        lg[k] = a + bq + b2[k];
    }
    float mx = lg[0];
#pragma unroll
    for (int k = 1; k < 25; k++) mx = fmaxf(mx, lg[k]);
    float e[25], sum = 0.f;
#pragma unroll
    for (int k = 0; k < 25; k++) { e[k] = __expf(lg[k] - mx); sum += e[k]; }
    const float inv = 1.f / sum;
    const int h = h0 + ty, w = w0 + tx;
    const size_t base = ((size_t)b * KK) * nHW + h * nW + w;
#pragma unroll
    for (int k = 0; k < 25; k++)
        g_ker[base + (size_t)k * nHW] = e[k] * inv;
}

// ---------------------------------------------------------------------------
// Kernel 3: softmax-weighted 5x5 window sum (R7-proven, verbatim).
// ---------------------------------------------------------------------------
__global__ void __launch_bounds__(256) k3_apply(
    const float* __restrict__ x, float* __restrict__ out)
{
    __shared__ float2 xi[2][2][35][38];

    const int t  = threadIdx.x;
    const int bz = blockIdx.z;
    const int b  = bz >> 2;
    const int cbase = (bz & 3) * 64;
    const int h0 = blockIdx.y * 16, w0 = blockIdx.x * 16;
    const int py = t >> 4, px = t & 15;
    const int h = h0 + py, w = w0 + px;

    constexpr int XI_BUF = 2 * 35 * 38;
    float2* xib = &xi[0][0][0][0];

    ull kp[25];
#pragma unroll
    for (int k = 0; k < 25; k++) {
        float kv = g_ker[((size_t)(b * KK + k)) * nHW + h * nW + w];
        kp[k] = pack2(kv, kv);
    }

    const int ir0 = 2 * h0 - 2, ic0 = 2 * w0 - 2;
    const float* xb = x + ((size_t)(b * C + cbase)) * HW;

    int xoff[10], xdi[10];
#pragma unroll
    for (int s = 0; s < 10; s++) {
        int idx = t + s * 256;
        xoff[s] = -1; xdi[s] = -1;
        if (idx < 2450) {
            int cp = (idx >= 1225) ? 1 : 0;
            int rr = idx - cp * 1225;
            int r = rr / 35, cc = rr - r * 35;
            int ir = ir0 + r, ic = ic0 + cc;
            xdi[s] = (cp * 35 + r) * 38 + cc;
            if ((unsigned)ir < 128u && (unsigned)ic < 128u)
                xoff[s] = cp * 2 * HW + ir * W + ic;
        }
    }

    float2 xv[10];
#pragma unroll
    for (int s = 0; s < 10; s++) {
        xv[s] = make_float2(0.f, 0.f);
        if (xoff[s] >= 0) {
            xv[s].x = xb[xoff[s]];
            xv[s].y = xb[xoff[s] + HW];
        }
    }
#pragma unroll
    for (int s = 0; s < 10; s++) if (xdi[s] >= 0) xib[xdi[s]] = xv[s];
    __syncthreads();

    int cur = 0;
#pragma unroll 1
    for (int it = 0; it < 16; it++) {
        if (it < 15) {
            const int coff = (it + 1) * 4 * HW;
#pragma unroll
            for (int s = 0; s < 10; s++) {
                xv[s] = make_float2(0.f, 0.f);
                if (xoff[s] >= 0) {
                    xv[s].x = xb[xoff[s] + coff];
                    xv[s].y = xb[xoff[s] + coff + HW];
                }
            }
        }

        const int c = cbase + it * 4;
#pragma unroll
        for (int cp = 0; cp < 2; cp++) {
            ull a[5];
#pragma unroll
            for (int i = 0; i < 5; i++) a[i] = 0ULL;
#pragma unroll
            for (int i = 0; i < 5; i++)
#pragma unroll
                for (int j = 0; j < 5; j++) {
                    ull xvv = *(const ull*)&xi[cur][cp][2 * py + i][2 * px + j];
                    const int k = i * 5 + j;
                    FMA2(a[k % 5], kp[k], xvv, a[k % 5]);
                }
            ull s01, s23, ssum;
            ADD2(s01, a[0], a[1]);
            ADD2(s23, a[2], a[3]);
            ADD2(s01, s01, s23);
            ADD2(ssum, s01, a[4]);
            float o0, o1; unpack2(ssum, o0, o1);
            const size_t obase = ((size_t)(b * C + c + 2 * cp)) * nHW + h * nW + w;
            out[obase]       = o0;
            out[obase + nHW] = o1;
        }

        if (it < 15) {
            const int nb = cur ^ 1;
#pragma unroll
            for (int s = 0; s < 10; s++)
                if (xdi[s] >= 0) xib[nb * XI_BUF + xdi[s]] = xv[s];
            __syncthreads();
        }
        cur ^= 1;
    }
}

// ---------------------------------------------------------------------------
extern "C" void kernel_launch(void* const* d_in, const int* in_sizes, int n_in,
                              void* d_out, int out_size)
{
    (void)in_sizes; (void)n_in; (void)out_size;
    const float* x  = (const float*)d_in[0];
    const float* w1 = (const float*)d_in[1];
    const float* b1 = (const float*)d_in[2];
    const float* w2 = (const float*)d_in[3];
    const float* b2 = (const float*)d_in[4];
    float* out = (float*)d_out;

    k1_conv1x1_tc<<<512, 256>>>(x, w1, b1);
    k2_encoder<<<dim3(4, 8, 8), 128>>>(w2, b2);
    k3_apply<<<dim3(4, 4, 32), 256>>>(x, out);
}